// round 6
// baseline (speedup 1.0000x reference)
#include <cuda_runtime.h>
#include <cuda_fp16.h>

// ---------------------------------------------------------------------------
// MetaPath2Vec skip-gram loss.
//
// R5: the kernel is pinned at the L2/LTS byte-throughput cap (~7.8 TB/s
// delivered; LDG and cp.async both measured 224-225us moving 1.76 GB).
// Only lever: move fewer bytes. Convert emb f32->fp16 into a 128 MB
// __device__ scratch table each call (deterministic), then gather fp16
// rows: gather traffic halves, and the fp16 table is ~L2-resident.
//
// Numerics (validated R3): sig = 1/(1+expf(-x)) in f32, literal
// sig+1e-15f / 1-sig+1e-15f terms. fp16 row quantization adds dot noise
// std ~4.5e-3 -> loss rel-err ~1e-5, far under the 1e-3 gate.
// Indices are int32 on device.
// ---------------------------------------------------------------------------

#define N_EMB 500001
#define DIM   128

// fp16 table: N_EMB rows x 256 B = 16 uint4 per row.
__device__ uint4 g_emb_h[(size_t)N_EMB * 16];
__device__ double g_acc[2];   // [0] = pos term sum, [1] = neg term sum

__global__ void zero_acc_kernel() {
    if (threadIdx.x < 2) g_acc[threadIdx.x] = 0.0;
}

// f32 -> fp16 conversion: each thread converts 8 floats (2x float4 in,
// 1x uint4 out). 64000128 floats = 8000016 groups.
__global__ void convert_kernel(const float* __restrict__ emb) {
    const size_t n_grp = (size_t)N_EMB * DIM / 8;   // 8000016
    const float4* src = reinterpret_cast<const float4*>(emb);
    size_t i = (size_t)blockIdx.x * blockDim.x + threadIdx.x;
    const size_t stride = (size_t)gridDim.x * blockDim.x;
    for (; i < n_grp; i += stride) {
        float4 a = src[2 * i];
        float4 b = src[2 * i + 1];
        __half2 h0 = __floats2half2_rn(a.x, a.y);
        __half2 h1 = __floats2half2_rn(a.z, a.w);
        __half2 h2 = __floats2half2_rn(b.x, b.y);
        __half2 h3 = __floats2half2_rn(b.z, b.w);
        uint4 o;
        o.x = *reinterpret_cast<unsigned*>(&h0);
        o.y = *reinterpret_cast<unsigned*>(&h1);
        o.z = *reinterpret_cast<unsigned*>(&h2);
        o.w = *reinterpret_cast<unsigned*>(&h3);
        g_emb_h[i] = o;
    }
}

__device__ __forceinline__ float warp_reduce_sum(float v) {
    v += __shfl_xor_sync(0xffffffffu, v, 16);
    v += __shfl_xor_sync(0xffffffffu, v, 8);
    v += __shfl_xor_sync(0xffffffffu, v, 4);
    v += __shfl_xor_sync(0xffffffffu, v, 2);
    v += __shfl_xor_sync(0xffffffffu, v, 1);
    return v;
}

// dot contribution of one lane's 8-byte slice (4 halfs) against h-slice
__device__ __forceinline__ float dot4(uint2 a, uint2 b) {
    __half2 a0 = *reinterpret_cast<__half2*>(&a.x);
    __half2 a1 = *reinterpret_cast<__half2*>(&a.y);
    __half2 b0 = *reinterpret_cast<__half2*>(&b.x);
    __half2 b1 = *reinterpret_cast<__half2*>(&b.y);
    float2 fa0 = __half22float2(a0), fa1 = __half22float2(a1);
    float2 fb0 = __half22float2(b0), fb1 = __half22float2(b1);
    return fa0.x * fb0.x + fa0.y * fb0.y + fa1.x * fb1.x + fa1.y * fb1.y;
}

// One warp per walk, grid-strided. Each lane reads an 8B slice of each
// fp16 row (warp = 256 B = 2 dense 128B lines per row).
__global__ void __launch_bounds__(128, 16)
walk_loss_kernel(const int* __restrict__ pos_rw,
                 const int* __restrict__ neg_rw,
                 int n_pos, int n_neg)
{
    __shared__ double sred[2][4];

    const int lane  = threadIdx.x & 31;
    const int wl    = threadIdx.x >> 5;
    const int gw    = (blockIdx.x * blockDim.x + threadIdx.x) >> 5;
    const int W     = (gridDim.x * blockDim.x) >> 5;
    const int total = n_pos + n_neg;

    double pos_acc = 0.0, neg_acc = 0.0;

    // prefetched indices for the current walk (lanes 0..6 active)
    int my = 0;
    if (gw < total) {
        const int* rw0 = (gw < n_pos) ? pos_rw + (size_t)gw * 7
                                      : neg_rw + (size_t)(gw - n_pos) * 7;
        if (lane < 7) my = rw0[lane];
    }

    const uint2* e = reinterpret_cast<const uint2*>(g_emb_h);

    for (int w = gw; w < total; w += W) {
        // prefetch next walk's indices
        int wn = w + W;
        int my_next = 0;
        if (wn < total && lane < 7) {
            const int* rwn = (wn < n_pos) ? pos_rw + (size_t)wn * 7
                                          : neg_rw + (size_t)(wn - n_pos) * 7;
            my_next = rwn[lane];
        }

        int i0 = __shfl_sync(0xffffffffu, my, 0);
        int i1 = __shfl_sync(0xffffffffu, my, 1);
        int i2 = __shfl_sync(0xffffffffu, my, 2);
        int i3 = __shfl_sync(0xffffffffu, my, 3);
        int i4 = __shfl_sync(0xffffffffu, my, 4);
        int i5 = __shfl_sync(0xffffffffu, my, 5);
        int i6 = __shfl_sync(0xffffffffu, my, 6);

        // issue all 7 row gathers back-to-back (14 lines in flight)
        uint2 h  = e[(size_t)i0 * 32 + lane];
        uint2 v1 = e[(size_t)i1 * 32 + lane];
        uint2 v2 = e[(size_t)i2 * 32 + lane];
        uint2 v3 = e[(size_t)i3 * 32 + lane];
        uint2 v4 = e[(size_t)i4 * 32 + lane];
        uint2 v5 = e[(size_t)i5 * 32 + lane];
        uint2 v6 = e[(size_t)i6 * 32 + lane];

        float d1 = dot4(h, v1);
        float d2 = dot4(h, v2);
        float d3 = dot4(h, v3);
        float d4 = dot4(h, v4);
        float d5 = dot4(h, v5);
        float d6 = dot4(h, v6);

        d1 = warp_reduce_sum(d1);
        d2 = warp_reduce_sum(d2);
        d3 = warp_reduce_sum(d3);
        d4 = warp_reduce_sum(d4);
        d5 = warp_reduce_sum(d5);
        d6 = warp_reduce_sum(d6);

        // 6 transcendental terms in parallel across lanes 0..5
        float dv = (lane == 0) ? d1 :
                   (lane == 1) ? d2 :
                   (lane == 2) ? d3 :
                   (lane == 3) ? d4 :
                   (lane == 4) ? d5 : d6;

        const bool is_pos = (w < n_pos);
        float sig  = 1.0f / (1.0f + expf(-dv));
        float arg  = is_pos ? (sig + 1e-15f) : (1.0f - sig + 1e-15f);
        float term = (lane < 6) ? (-logf(arg)) : 0.0f;

        term = warp_reduce_sum(term);
        if (lane == 0) {
            if (is_pos) pos_acc += (double)term;
            else        neg_acc += (double)term;
        }

        my = my_next;
    }

    if (lane == 0) { sred[0][wl] = pos_acc; sred[1][wl] = neg_acc; }
    __syncthreads();

    if (threadIdx.x == 0) {
        double p = sred[0][0] + sred[0][1] + sred[0][2] + sred[0][3];
        double n = sred[1][0] + sred[1][1] + sred[1][2] + sred[1][3];
        atomicAdd(&g_acc[0], p);
        atomicAdd(&g_acc[1], n);
    }
}

__global__ void finalize_kernel(float* out, int n_pos, int n_neg) {
    if (threadIdx.x == 0) {
        double pos_loss = g_acc[0] / ((double)n_pos * 6.0);
        double neg_loss = g_acc[1] / ((double)n_neg * 6.0);
        out[0] = (float)(pos_loss + neg_loss);
    }
}

extern "C" void kernel_launch(void* const* d_in, const int* in_sizes, int n_in,
                              void* d_out, int out_size)
{
    const float* emb    = (const float*)d_in[0];
    const int*   pos_rw = (const int*)d_in[1];
    const int*   neg_rw = (const int*)d_in[2];

    const int n_pos = in_sizes[1] / 7;   // 81920
    const int n_neg = in_sizes[2] / 7;   // 409600

    zero_acc_kernel<<<1, 32>>>();
    convert_kernel<<<148 * 16, 256>>>(emb);

    // 148 SMs x 16 CTAs x 4 warps = 9472 warps, ~52 walks/warp grid-stride
    walk_loss_kernel<<<148 * 16, 128>>>(pos_rw, neg_rw, n_pos, n_neg);

    finalize_kernel<<<1, 32>>>((float*)d_out, n_pos, n_neg);
}